// round 15
// baseline (speedup 1.0000x reference)
#include <cuda_runtime.h>
#include <cstdint>

#define ND 128
#define MAX_NODES 100000
#define MAX_EDGES 625000
#define TM 128
#define KCH 32
#define NT 128          // node kernel threads
#define NTF 256         // fused kernel threads

// node kernel dynamic smem: Xs[2][TM][36] | Bs[2][4096]
#define XS_FLOATS (2 * TM * 36)
#define BS_FLOATS (2 * 4096)
#define DSM_BYTES ((XS_FLOATS + BS_FLOATS) * 4)

// fused kernel dynamic smem: Xs[3][TM][36] | BsW[3][4096] | BsP[3][4096]
#define FX_FLOATS (3 * TM * 36)
#define FB_FLOATS (3 * 4096)
#define FDSM_BYTES ((FX_FLOATS + 2 * FB_FLOATS) * 4)

// ---------------- device scratch (allocation-free rule) ---------------------
__device__ float g_agg[(size_t)MAX_NODES * ND];
__device__ float g_deg[MAX_NODES];
// Fragment-ordered tf32 weight images, lane-contiguous float4 layout:
// idx = ((((ks*2 + half)*4 + j)*32 + lane)*4 + t), nat = 2j+(t>>1), pair = t&1,
// n = half*64 + nat*8 + (lane>>2), k = ks*8 + (lane&3) + pair*4.
// One K-chunk (4 ksteps) = 4096 floats = 16KB contiguous.
// g_Pfrag is built against the FUSED X column space [e|h_src]: source P row
// = (k<128 ? k+128 : k-128).
__device__ float g_Pfrag[(256 / 8) * 2 * 4 * 32 * 4];
__device__ float g_Qfrag[(256 / 8) * 2 * 4 * 32 * 4];
__device__ float g_Wfrag[(384 / 8) * 2 * 4 * 32 * 4];

__device__ __forceinline__ uint32_t tf32_bits(float x) {
    uint32_t r;
    asm("cvt.rna.tf32.f32 %0, %1;" : "=r"(r) : "f"(x));
    return r;
}
__device__ __forceinline__ float tf32f(float x) { return __uint_as_float(tf32_bits(x)); }

__device__ __forceinline__ uint32_t smem_u32(const void* p) {
    uint32_t a;
    asm("{ .reg .u64 t; cvta.to.shared.u64 t, %1; cvt.u32.u64 %0, t; }"
        : "=r"(a) : "l"(p));
    return a;
}
__device__ __forceinline__ void cp_async16(uint32_t dst, const void* src) {
    asm volatile("cp.async.cg.shared.global [%0], [%1], 16;"
                 :: "r"(dst), "l"(src) : "memory");
}
#define CP_COMMIT() asm volatile("cp.async.commit_group;" ::: "memory")
#define CP_WAIT0()  asm volatile("cp.async.wait_group 0;" ::: "memory")
#define CP_WAIT1()  asm volatile("cp.async.wait_group 1;" ::: "memory")

__device__ __forceinline__ void mma_tf32(float* c, const uint32_t* a, const uint32_t* b) {
    asm volatile(
        "mma.sync.aligned.m16n8k8.row.col.f32.tf32.tf32.f32 "
        "{%0,%1,%2,%3}, {%4,%5,%6,%7}, {%8,%9}, {%0,%1,%2,%3};"
        : "+f"(c[0]), "+f"(c[1]), "+f"(c[2]), "+f"(c[3])
        : "r"(a[0]), "r"(a[1]), "r"(a[2]), "r"(a[3]), "r"(b[0]), "r"(b[1]));
}
__device__ __forceinline__ void red_add_v2(float* ptr, float v0, float v1) {
    asm volatile("red.global.add.v2.f32 [%0], {%1,%2};"
                 :: "l"(ptr), "f"(v0), "f"(v1) : "memory");
}

// ---------------- prep: zero agg/deg, build fragment-ordered weights --------
__global__ void prep_kernel(const float* __restrict__ Pw, const float* __restrict__ Qw,
                            const float* __restrict__ Ww, int n_nodes) {
    int stride = gridDim.x * blockDim.x;
    int t0 = blockIdx.x * blockDim.x + threadIdx.x;
    for (int i = t0; i < n_nodes * ND; i += stride) g_agg[i] = 0.0f;
    for (int i = t0; i < n_nodes; i += stride) g_deg[i] = 0.0f;
    for (int i = t0; i < (256 / 8) * 2 * 4 * 32 * 4; i += stride) {
        int t = i & 3, lane = (i >> 2) & 31, j = (i >> 7) & 3, wn = (i >> 9) & 1, ks = i >> 10;
        int nat = 2 * j + (t >> 1), pair = t & 1;
        int n = wn * 64 + nat * 8 + (lane >> 2);
        int k = ks * 8 + (lane & 3) + pair * 4;
        int kp = (k < 128) ? (k + 128) : (k - 128);   // fused X col -> P row
        g_Pfrag[i] = tf32f(Pw[kp * ND + n]);
        g_Qfrag[i] = tf32f(Qw[k * ND + n]);
    }
    for (int i = t0; i < (384 / 8) * 2 * 4 * 32 * 4; i += stride) {
        int t = i & 3, lane = (i >> 2) & 31, j = (i >> 7) & 3, wn = (i >> 9) & 1, ks = i >> 10;
        int nat = 2 * j + (t >> 1), pair = t & 1;
        int n = wn * 64 + nat * 8 + (lane >> 2);
        int k = ks * 8 + (lane & 3) + pair * 4;
        g_Wfrag[i] = tf32f(Ww[k * ND + n]);
    }
}

// ---------------- fused msg+edge kernel -------------------------------------
// 8 warps, warp tile 64x32 for BOTH outputs, CTA tile 128x128 (x2 GEMMs).
// X = [e | h_src | h_tgt], K=384 (12 chunks). Edge GEMM uses all chunks;
// msg GEMM uses chunks 0..7 with the k-permuted P image. 3-stage pipeline.
__global__ __launch_bounds__(NTF, 1)
void fused_kernel(const float* __restrict__ h, const float* __restrict__ e,
                  const int* __restrict__ src, const int* __restrict__ tgt,
                  const float* __restrict__ Pb, const float* __restrict__ Wb,
                  float* __restrict__ out_e, int n_edges) {
    extern __shared__ float dsm[];
    float* Xs  = dsm;                       // [3][TM][36]
    float* BsW = dsm + FX_FLOATS;           // [3][4096]
    float* BsP = BsW + FB_FLOATS;           // [3][4096]
    __shared__ int s_src[TM];
    __shared__ int s_tgt[TM];
    __shared__ float s_biasP[ND];
    __shared__ float s_biasW[ND];

    const int tid = threadIdx.x;
    const int wid = tid >> 5;
    const int lane = tid & 31;
    const int r0 = blockIdx.x * TM;

    if (tid < TM) {
        int r = r0 + tid;
        bool ok = r < n_edges;
        s_src[tid] = ok ? src[r] : 0;
        s_tgt[tid] = ok ? tgt[r] : 0;
    }
    if (tid < ND) {
        s_biasP[tid] = Pb[tid];
        s_biasW[tid] = Wb[tid];
    }
    __syncthreads();

    const uint32_t xs_base = smem_u32(Xs);
    const uint32_t bw_base = smem_u32(BsW);
    const uint32_t bp_base = smem_u32(BsP);

    const int wm = wid >> 2;       // 2 row-groups of 64
    const int wn = wid & 3;        // 4 col-quarters of 32
    const int m_base = wm * 64;
    const int half = wn >> 1;      // image half
    const int jpair = wn & 1;      // j-pair within half
    const int g = lane >> 2;
    const int tg = lane & 3;

    float cE[4][4][4];             // edge accum: 4 m-mats x 4 n-mats
    float cM[4][4][4];             // msg accum
#pragma unroll
    for (int i = 0; i < 4; i++)
#pragma unroll
        for (int j = 0; j < 4; j++)
#pragma unroll
            for (int t = 0; t < 4; t++) { cE[i][j][t] = 0.0f; cM[i][j][t] = 0.0f; }

    auto issue_chunk = [&](int q, int b) {
        const int kk = q * KCH;
#pragma unroll
        for (int i = tid; i < TM * 8; i += NTF) {
            int r = i >> 3;
            int s = i & 7;
            int gr = r0 + r;
            int grc = (gr < n_edges) ? gr : 0;
            int k = kk + s * 4;
            const float* p;
            if (k < 128)      p = e + (size_t)grc * ND + k;
            else if (k < 256) p = h + (size_t)s_src[r] * ND + (k - 128);
            else              p = h + (size_t)s_tgt[r] * ND + (k - 256);
            cp_async16(xs_base + (((b * TM) + r) * 36 + s * 4) * 4, p);
        }
        const float* wsrc = g_Wfrag + (size_t)q * 4096;
#pragma unroll
        for (int i = tid; i < 1024; i += NTF)
            cp_async16(bw_base + (b * 4096 + i * 4) * 4, wsrc + i * 4);
        if (q < 8) {
            const float* psrc = g_Pfrag + (size_t)q * 4096;
#pragma unroll
            for (int i = tid; i < 1024; i += NTF)
                cp_async16(bp_base + (b * 4096 + i * 4) * 4, psrc + i * 4);
        }
        CP_COMMIT();
    };

    const int NCH = 12;
    issue_chunk(0, 0);
    issue_chunk(1, 1);

    for (int q = 0; q < NCH; q++) {
        const int b = q % 3;
        if (q == NCH - 1) { CP_WAIT0(); } else { CP_WAIT1(); }
        __syncthreads();
        if (q + 2 < NCH) issue_chunk(q + 2, (q + 2) % 3);

        const float* Xb = Xs + b * TM * 36;
        const float* BWb = BsW + b * 4096;
        const float* BPb = BsP + b * 4096;
        const bool do_msg = (q < 8);

#pragma unroll
        for (int ks = 0; ks < 4; ks++) {
            const int k0 = ks * 8;
            uint32_t a[4][4];
#pragma unroll
            for (int mb = 0; mb < 4; mb++) {
                int mr = m_base + mb * 16;
                a[mb][0] = tf32_bits(Xb[(mr + g) * 36 + k0 + tg]);
                a[mb][1] = tf32_bits(Xb[(mr + g + 8) * 36 + k0 + tg]);
                a[mb][2] = tf32_bits(Xb[(mr + g) * 36 + k0 + tg + 4]);
                a[mb][3] = tf32_bits(Xb[(mr + g + 8) * 36 + k0 + tg + 4]);
            }
            // edge B: 2 conflict-free LDS.128 -> 4 n-mats
            {
                const float4* bp4 = (const float4*)(BWb + ((ks * 2 + half) * 4 + jpair * 2) * 128) + lane;
                float4 f0 = bp4[0];
                float4 f1 = bp4[32];
                uint32_t bb[4][2];
                bb[0][0] = __float_as_uint(f0.x); bb[0][1] = __float_as_uint(f0.y);
                bb[1][0] = __float_as_uint(f0.z); bb[1][1] = __float_as_uint(f0.w);
                bb[2][0] = __float_as_uint(f1.x); bb[2][1] = __float_as_uint(f1.y);
                bb[3][0] = __float_as_uint(f1.z); bb[3][1] = __float_as_uint(f1.w);
#pragma unroll
                for (int mb = 0; mb < 4; mb++)
#pragma unroll
                    for (int nt2 = 0; nt2 < 4; nt2++)
                        mma_tf32(cE[mb][nt2], a[mb], bb[nt2]);
            }
            // msg B (chunks 0..7)
            if (do_msg) {
                const float4* bp4 = (const float4*)(BPb + ((ks * 2 + half) * 4 + jpair * 2) * 128) + lane;
                float4 f0 = bp4[0];
                float4 f1 = bp4[32];
                uint32_t bb[4][2];
                bb[0][0] = __float_as_uint(f0.x); bb[0][1] = __float_as_uint(f0.y);
                bb[1][0] = __float_as_uint(f0.z); bb[1][1] = __float_as_uint(f0.w);
                bb[2][0] = __float_as_uint(f1.x); bb[2][1] = __float_as_uint(f1.y);
                bb[3][0] = __float_as_uint(f1.z); bb[3][1] = __float_as_uint(f1.w);
#pragma unroll
                for (int mb = 0; mb < 4; mb++)
#pragma unroll
                    for (int nt2 = 0; nt2 < 4; nt2++)
                        mma_tf32(cM[mb][nt2], a[mb], bb[nt2]);
            }
        }
        __syncthreads();
    }

    // ---- epilogue ----
#pragma unroll
    for (int mb = 0; mb < 4; mb++) {
        int row0 = m_base + mb * 16 + g;
        int row1 = row0 + 8;
        int gr0 = r0 + row0;
        int gr1 = r0 + row1;
#pragma unroll
        for (int nt2 = 0; nt2 < 4; nt2++) {
            int col = wn * 32 + nt2 * 8 + tg * 2;
            // edge output
            {
                float b0 = s_biasW[col], b1 = s_biasW[col + 1];
                if (gr0 < n_edges)
                    *(float2*)&out_e[(size_t)gr0 * ND + col] =
                        make_float2(fmaxf(cE[mb][nt2][0] + b0, 0.0f),
                                    fmaxf(cE[mb][nt2][1] + b1, 0.0f));
                if (gr1 < n_edges)
                    *(float2*)&out_e[(size_t)gr1 * ND + col] =
                        make_float2(fmaxf(cE[mb][nt2][2] + b0, 0.0f),
                                    fmaxf(cE[mb][nt2][3] + b1, 0.0f));
            }
            // msg scatter
            {
                float b0 = s_biasP[col], b1 = s_biasP[col + 1];
                if (gr0 < n_edges)
                    red_add_v2(&g_agg[(size_t)s_tgt[row0] * ND + col],
                               fmaxf(cM[mb][nt2][0] + b0, 0.0f),
                               fmaxf(cM[mb][nt2][1] + b1, 0.0f));
                if (gr1 < n_edges)
                    red_add_v2(&g_agg[(size_t)s_tgt[row1] * ND + col],
                               fmaxf(cM[mb][nt2][2] + b0, 0.0f),
                               fmaxf(cM[mb][nt2][3] + b1, 0.0f));
            }
        }
        if (wn == 0 && tg == 0) {
            if (gr0 < n_edges) atomicAdd(&g_deg[s_tgt[row0]], 1.0f);
            if (gr1 < n_edges) atomicAdd(&g_deg[s_tgt[row1]], 1.0f);
        }
    }
}

// ---------------- node kernel (unchanged structure from R14) ----------------
__global__ __launch_bounds__(NT, 2)
void node_kernel(const float* __restrict__ h, const float* __restrict__ bias,
                 float* __restrict__ out, int n_rows) {
    extern __shared__ float dsm[];
    float* Xs = dsm;                     // [2][TM][36]
    float* Bs = dsm + XS_FLOATS;         // [2][4096]
    __shared__ float s_inv[TM];
    __shared__ float s_bias[ND];

    const int tid = threadIdx.x;
    const int wid = tid >> 5;
    const int lane = tid & 31;
    const int r0 = blockIdx.x * TM;

    {
        int r = r0 + tid;
        s_inv[tid] = (r < n_rows) ? (1.0f / fmaxf(g_deg[r], 1.0f)) : 0.0f;
        s_bias[tid] = bias[tid];
    }
    __syncthreads();

    const uint32_t xs_base = smem_u32(Xs);
    const uint32_t bs_base = smem_u32(Bs);

    const int wm = wid >> 1;
    const int wn = wid & 1;
    const int m_base = wm * 64;
    const int n_base = wn * 64;
    const int g = lane >> 2;
    const int tg = lane & 3;

    float c[4][8][4];
#pragma unroll
    for (int i = 0; i < 4; i++)
#pragma unroll
        for (int j = 0; j < 8; j++)
#pragma unroll
            for (int t = 0; t < 4; t++) c[i][j][t] = 0.0f;

    auto issue_chunk = [&](int q, int b) {
        const int kk = q * KCH;
#pragma unroll
        for (int i = tid; i < TM * 8; i += NT) {
            int r = i >> 3;
            int s = i & 7;
            int gr = r0 + r;
            int grc = (gr < n_rows) ? gr : 0;
            int k = kk + s * 4;
            const float* p = (k < 128) ? h + (size_t)grc * ND + k
                                       : g_agg + (size_t)grc * ND + (k - 128);
            cp_async16(xs_base + (((b * TM) + r) * 36 + s * 4) * 4, p);
        }
        const float* bsrc = g_Qfrag + (size_t)q * 4096;
#pragma unroll
        for (int i = tid; i < 1024; i += NT)
            cp_async16(bs_base + (b * 4096 + i * 4) * 4, bsrc + i * 4);
        CP_COMMIT();
    };

    const int NCH = 8;
    issue_chunk(0, 0);

    for (int q = 0; q < NCH; q++) {
        const int b = q & 1;
        const int kk = q * KCH;
        CP_WAIT0();
        __syncthreads();
        if (q + 1 < NCH) issue_chunk(q + 1, (q + 1) & 1);

        float sA[8];
#pragma unroll
        for (int i = 0; i < 8; i++) sA[i] = 1.0f;
        if (kk >= 128) {
#pragma unroll
            for (int mb = 0; mb < 4; mb++) {
                sA[mb * 2]     = s_inv[m_base + mb * 16 + g];
                sA[mb * 2 + 1] = s_inv[m_base + mb * 16 + 8 + g];
            }
        }

        const float* Xb = Xs + b * TM * 36;
        const float* Bb = Bs + b * 4096;
#pragma unroll
        for (int ks = 0; ks < 4; ks++) {
            const int k0 = ks * 8;
            uint32_t a[4][4];
#pragma unroll
            for (int mb = 0; mb < 4; mb++) {
                int mr = m_base + mb * 16;
                a[mb][0] = tf32_bits(Xb[(mr + g) * 36 + k0 + tg]         * sA[mb * 2]);
                a[mb][1] = tf32_bits(Xb[(mr + g + 8) * 36 + k0 + tg]     * sA[mb * 2 + 1]);
                a[mb][2] = tf32_bits(Xb[(mr + g) * 36 + k0 + tg + 4]     * sA[mb * 2]);
                a[mb][3] = tf32_bits(Xb[(mr + g + 8) * 36 + k0 + tg + 4] * sA[mb * 2 + 1]);
            }
            const float4* bp = (const float4*)(Bb + ((ks * 2 + wn) * 4) * 128) + lane;
            float4 bf0 = bp[0];
            float4 bf1 = bp[32];
            float4 bf2 = bp[64];
            float4 bf3 = bp[96];
            uint32_t bb[8][2];
            bb[0][0] = __float_as_uint(bf0.x); bb[0][1] = __float_as_uint(bf0.y);
            bb[1][0] = __float_as_uint(bf0.z); bb[1][1] = __float_as_uint(bf0.w);
            bb[2][0] = __float_as_uint(bf1.x); bb[2][1] = __float_as_uint(bf1.y);
            bb[3][0] = __float_as_uint(bf1.z); bb[3][1] = __float_as_uint(bf1.w);
            bb[4][0] = __float_as_uint(bf2.x); bb[4][1] = __float_as_uint(bf2.y);
            bb[5][0] = __float_as_uint(bf2.z); bb[5][1] = __float_as_uint(bf2.w);
            bb[6][0] = __float_as_uint(bf3.x); bb[6][1] = __float_as_uint(bf3.y);
            bb[7][0] = __float_as_uint(bf3.z); bb[7][1] = __float_as_uint(bf3.w);
#pragma unroll
            for (int mb = 0; mb < 4; mb++)
#pragma unroll
                for (int nat = 0; nat < 8; nat++)
                    mma_tf32(c[mb][nat], a[mb], bb[nat]);
        }
        __syncthreads();
    }

#pragma unroll
    for (int mb = 0; mb < 4; mb++) {
        int row0 = m_base + mb * 16 + g;
        int row1 = row0 + 8;
        int gr0 = r0 + row0;
        int gr1 = r0 + row1;
#pragma unroll
        for (int nat = 0; nat < 8; nat++) {
            int col = n_base + nat * 8 + tg * 2;
            float b0 = s_bias[col], b1 = s_bias[col + 1];
            if (gr0 < n_rows)
                *(float2*)&out[(size_t)gr0 * ND + col] =
                    make_float2(fmaxf(c[mb][nat][0] + b0, 0.0f),
                                fmaxf(c[mb][nat][1] + b1, 0.0f));
            if (gr1 < n_rows)
                *(float2*)&out[(size_t)gr1 * ND + col] =
                    make_float2(fmaxf(c[mb][nat][2] + b0, 0.0f),
                                fmaxf(c[mb][nat][3] + b1, 0.0f));
        }
    }
}

// ---------------- launch ----------------------------------------------------
extern "C" void kernel_launch(void* const* d_in, const int* in_sizes, int n_in,
                              void* d_out, int out_size) {
    // metadata order: h, e, edge_index(int32), P_w, P_b, Q_w, Q_b, W_w, W_b
    const float* h   = (const float*)d_in[0];
    const float* e   = (const float*)d_in[1];
    const int*   idx = (const int*)d_in[2];
    const float* Pw  = (const float*)d_in[3];
    const float* Pb  = (const float*)d_in[4];
    const float* Qw  = (const float*)d_in[5];
    const float* Qb  = (const float*)d_in[6];
    const float* Ww  = (const float*)d_in[7];
    const float* Wb  = (const float*)d_in[8];

    int n_nodes = in_sizes[0] / ND;
    int n_edges = in_sizes[1] / ND;
    const int* src = idx;
    const int* tgt = idx + n_edges;

    float* out_h = (float*)d_out;
    float* out_e = out_h + (size_t)n_nodes * ND;

    cudaFuncSetAttribute(fused_kernel,
                         cudaFuncAttributeMaxDynamicSharedMemorySize, FDSM_BYTES);
    cudaFuncSetAttribute(node_kernel,
                         cudaFuncAttributeMaxDynamicSharedMemorySize, DSM_BYTES);

    prep_kernel<<<256, 256>>>(Pw, Qw, Ww, n_nodes);

    int eb = (n_edges + TM - 1) / TM;
    int nb = (n_nodes + TM - 1) / TM;
    fused_kernel<<<eb, NTF, FDSM_BYTES>>>(h, e, src, tgt, Pb, Wb, out_e, n_edges);
    node_kernel<<<nb, NT, DSM_BYTES>>>(h, Qb, out_h, n_nodes);
}